// round 1
// baseline (speedup 1.0000x reference)
#include <cuda_runtime.h>
#include <math.h>

#define BB 8
#define CIN 96
#define CC 192
#define HH 128
#define WW 128
#define WS 8
#define HEADS 8
#define HD 24
#define NWIN 2048
#define TT 131072
#define FF 768

// ---------------- scratch (device globals; no allocation allowed) ----------------
__device__ float g_xp[BB*CC*HH*WW];
__device__ float g_vp[BB*CC*HH*WW];
__device__ float g_xs[TT*CC];
__device__ float g_vs[TT*CC];
__device__ float g_q [TT*CC];
__device__ float g_kv[TT*2*CC];
__device__ float g_at[TT*CC];
__device__ float g_pr[TT*CC];
__device__ float g_l3[TT*CC];
__device__ float g_h1[(long)TT*FF];
__device__ float g_m [TT*CC];
__device__ float g_l4[TT*CC];

// ---------------- conv3x3: 96->192, pad 1, NCHW ----------------
// block: 32x32 spatial tile, 16 output channels; thread: 2x2 pixels x 16 OC
__global__ __launch_bounds__(256) void conv3x3_kernel(
    const float* __restrict__ in, const float* __restrict__ wgt,
    const float* __restrict__ bias, float* __restrict__ out)
{
    __shared__ float s_in[8][34][34];
    __shared__ float s_w[16][8][9];
    int tid = threadIdx.x;
    int xt = blockIdx.x;            // 0..3
    int byt = blockIdx.y;           // b*4 + yt
    int b = byt >> 2, yt = byt & 3;
    int ocb = blockIdx.z;           // 0..11
    int x0 = xt*32, y0 = yt*32;
    int px = (tid & 15)*2, py = (tid >> 4)*2;

    float acc[4][16];
    #pragma unroll
    for (int p=0;p<4;p++)
        #pragma unroll
        for (int o=0;o<16;o++) acc[p][o]=0.f;

    for (int icb = 0; icb < 12; icb++) {
        for (int e = tid; e < 8*34*34; e += 256) {
            int ic = e / 1156; int r = e % 1156;
            int yy = r / 34, xx = r % 34;
            int gy = y0 + yy - 1, gx = x0 + xx - 1;
            float v = 0.f;
            if (gy >= 0 && gy < HH && gx >= 0 && gx < WW)
                v = in[((b*CIN + icb*8 + ic)*HH + gy)*WW + gx];
            s_in[ic][yy][xx] = v;
        }
        for (int e = tid; e < 16*8*9; e += 256) {
            int oc = e / 72; int r = e % 72;
            int ic = r / 9, k = r % 9;
            s_w[oc][ic][k] = wgt[((ocb*16+oc)*CIN + icb*8+ic)*9 + k];
        }
        __syncthreads();
        for (int ic = 0; ic < 8; ic++) {
            #pragma unroll
            for (int ky = 0; ky < 3; ky++)
            #pragma unroll
            for (int kx = 0; kx < 3; kx++) {
                float i00 = s_in[ic][py+ky  ][px+kx  ];
                float i01 = s_in[ic][py+ky  ][px+kx+1];
                float i10 = s_in[ic][py+ky+1][px+kx  ];
                float i11 = s_in[ic][py+ky+1][px+kx+1];
                #pragma unroll
                for (int o = 0; o < 16; o++) {
                    float wv = s_w[o][ic][ky*3+kx];
                    acc[0][o] += i00*wv;
                    acc[1][o] += i01*wv;
                    acc[2][o] += i10*wv;
                    acc[3][o] += i11*wv;
                }
            }
        }
        __syncthreads();
    }
    #pragma unroll
    for (int o = 0; o < 16; o++) {
        float bb = bias[ocb*16+o];
        long base = ((long)(b*CC + ocb*16+o)*HH + y0+py)*WW + x0+px;
        out[base]          = acc[0][o] + bb;
        out[base+1]        = acc[1][o] + bb;
        out[base+WW]       = acc[2][o] + bb;
        out[base+WW+1]     = acc[3][o] + bb;
    }
}

// ---------------- LN over channels + window partition (NCHW -> [token][c]) ----------------
__global__ __launch_bounds__(256) void ln_win_kernel(
    const float* __restrict__ in, const float* __restrict__ gamma,
    const float* __restrict__ beta, float* __restrict__ out)
{
    __shared__ float s[32][193];
    __shared__ float s_mean[32], s_rstd[32];
    int bx = blockIdx.x;                 // 0..4095
    int wi = bx >> 1, half = bx & 1;
    int b = wi >> 8, wy = (wi >> 4) & 15, wx = wi & 15;
    int y0 = wy*8, x0 = wx*8;
    int tid = threadIdx.x;
    for (int e = tid; e < 32*192; e += 256) {
        int c = e >> 5, pl = e & 31;
        int p = half*32 + pl;
        int iy = p >> 3, ix = p & 7;
        s[pl][c] = in[((long)(b*CC + c)*HH + y0+iy)*WW + x0+ix];
    }
    __syncthreads();
    if (tid < 32) {
        float sum=0.f, sq=0.f;
        for (int c=0;c<CC;c++){ float v=s[tid][c]; sum+=v; sq+=v*v; }
        float mean = sum * (1.f/CC);
        float var = sq * (1.f/CC) - mean*mean;
        s_mean[tid]=mean; s_rstd[tid]=rsqrtf(var + 1e-5f);
    }
    __syncthreads();
    long base = ((long)wi*64 + half*32) * CC;
    for (int e = tid; e < 32*192; e += 256) {
        int pl = e / 192, c = e % 192;
        out[base + e] = (s[pl][c]-s_mean[pl])*s_rstd[pl]*gamma[c] + beta[c];
    }
}

// ---------------- SGEMM: C[MxN] = epi( A[MxK] * B[NxK]^T ) ----------------
template<bool HAS_BIAS, bool DO_GELU>
__global__ __launch_bounds__(256) void sgemm_nt(
    const float* __restrict__ A, const float* __restrict__ Bm,
    const float* __restrict__ bias, float* __restrict__ Cm,
    int M, int N, int K, float alpha)
{
    __shared__ float As[16][68];
    __shared__ float Bs[16][68];
    int tid = threadIdx.x;
    int bm = blockIdx.y * 64, bn = blockIdx.x * 64;
    int tm = tid >> 4, tn = tid & 15;
    float acc[4][4] = {};
    for (int kt = 0; kt < K; kt += 16) {
        #pragma unroll
        for (int l = 0; l < 4; l++) {
            int e = tid + l*256;
            int m = e >> 4, k = e & 15;
            As[k][m] = A[(long)(bm+m)*K + kt + k];
            Bs[k][m] = Bm[(long)(bn+m)*K + kt + k];
        }
        __syncthreads();
        #pragma unroll
        for (int k = 0; k < 16; k++) {
            float a[4], bv[4];
            #pragma unroll
            for (int i=0;i<4;i++) a[i] = As[k][tm*4+i];
            #pragma unroll
            for (int j=0;j<4;j++) bv[j] = Bs[k][tn*4+j];
            #pragma unroll
            for (int i=0;i<4;i++)
            #pragma unroll
            for (int j=0;j<4;j++)
                acc[i][j] += a[i]*bv[j];
        }
        __syncthreads();
    }
    #pragma unroll
    for (int i=0;i<4;i++) {
        long row = bm + tm*4 + i;
        #pragma unroll
        for (int j=0;j<4;j++) {
            int col = bn + tn*4 + j;
            float v = acc[i][j];
            if (HAS_BIAS) v += bias[col];
            v *= alpha;
            if (DO_GELU) v = 0.5f*v*(1.f + erff(v*0.70710678118654752f));
            Cm[row*N + col] = v;
        }
    }
}

// ---------------- windowed attention (block = window, loop heads) ----------------
__global__ __launch_bounds__(256) void attn_kernel(
    const float* __restrict__ q, const float* __restrict__ kv,
    const float* __restrict__ rpb, float* __restrict__ out)
{
    __shared__ float qs[64][25], ks[64][25], vs[64][25];
    __shared__ float sc[64][65];
    int w = blockIdx.x;
    int tid = threadIdx.x;
    long tb = (long)w * 64;
    for (int h = 0; h < HEADS; h++) {
        for (int e = tid; e < 64*24; e += 256) {
            int p = e / 24, d = e % 24;
            qs[p][d] = q [(tb+p)*CC    + h*HD + d];
            ks[p][d] = kv[(tb+p)*2*CC  + h*HD + d];
            vs[p][d] = kv[(tb+p)*2*CC  + CC + h*HD + d];
        }
        __syncthreads();
        {
            int i = tid >> 2, jg = tid & 3;
            #pragma unroll
            for (int jj = 0; jj < 16; jj++) {
                int j = jg*16 + jj;
                float s = 0.f;
                #pragma unroll
                for (int d = 0; d < 24; d++) s += qs[i][d]*ks[j][d];
                int ry = (i>>3) - (j>>3) + 7;
                int rx = (i&7)  - (j&7)  + 7;
                s += rpb[(ry*15+rx)*HEADS + h];
                sc[i][j] = s;
            }
        }
        __syncthreads();
        if (tid < 64) {
            float mx = -1e30f;
            for (int j=0;j<64;j++) mx = fmaxf(mx, sc[tid][j]);
            float sum = 0.f;
            for (int j=0;j<64;j++){ float e_ = expf(sc[tid][j]-mx); sc[tid][j]=e_; sum+=e_; }
            float inv = 1.f/sum;
            for (int j=0;j<64;j++) sc[tid][j] *= inv;
        }
        __syncthreads();
        for (int e = tid; e < 64*24; e += 256) {
            int p = e / 24, d = e % 24;
            float s = 0.f;
            #pragma unroll
            for (int j=0;j<64;j++) s += sc[p][j]*vs[j][d];
            out[(tb+p)*CC + h*HD + d] = s;
        }
        __syncthreads();
    }
}

// ---------------- row LN over 192 channels (token-contiguous) ----------------
__global__ __launch_bounds__(256) void ln_rows_kernel(
    const float* __restrict__ in, const float* __restrict__ gamma,
    const float* __restrict__ beta, float* __restrict__ out)
{
    int warp = threadIdx.x >> 5, lane = threadIdx.x & 31;
    long row = (long)blockIdx.x*8 + warp;
    const float* p = in + row*CC;
    float v[6];
    float sum=0.f, sq=0.f;
    #pragma unroll
    for (int k=0;k<6;k++){ v[k]=p[lane + k*32]; sum+=v[k]; sq+=v[k]*v[k]; }
    #pragma unroll
    for (int o=16;o>0;o>>=1){ sum += __shfl_xor_sync(~0u,sum,o); sq += __shfl_xor_sync(~0u,sq,o); }
    float mean = sum*(1.f/CC), var = sq*(1.f/CC) - mean*mean;
    float rstd = rsqrtf(var + 1e-5f);
    float* qo = out + row*CC;
    #pragma unroll
    for (int k=0;k<6;k++){ int c = lane+k*32; qo[c] = (v[k]-mean)*rstd*gamma[c] + beta[c]; }
}

// ---------------- window reverse + residual add, write NCHW ----------------
__global__ __launch_bounds__(256) void final_kernel(
    const float* __restrict__ mln, const float* __restrict__ xp,
    const float* __restrict__ vp, float* __restrict__ out)
{
    __shared__ float s[32][193];
    int bx = blockIdx.x;
    int wi = bx >> 1, half = bx & 1;
    int b = wi >> 8, wy = (wi >> 4) & 15, wx = wi & 15;
    int y0 = wy*8, x0 = wx*8;
    int tid = threadIdx.x;
    long base = ((long)wi*64 + half*32)*CC;
    for (int e = tid; e < 32*192; e += 256) {
        int pl = e / 192, c = e % 192;
        s[pl][c] = mln[base + e];
    }
    __syncthreads();
    for (int e = tid; e < 32*192; e += 256) {
        int c = e >> 5, pl = e & 31;
        int p = half*32 + pl;
        int iy = p >> 3, ix = p & 7;
        long idx = ((long)(b*CC + c)*HH + y0+iy)*WW + x0+ix;
        out[idx] = s[pl][c] + xp[idx] + vp[idx];
    }
}

extern "C" void kernel_launch(void* const* d_in, const int* in_sizes, int n_in,
                              void* d_out, int out_size)
{
    const float* x    = (const float*)d_in[0];
    const float* v    = (const float*)d_in[1];
    const float* pq_w = (const float*)d_in[2];
    const float* pq_b = (const float*)d_in[3];
    const float* pv_w = (const float*)d_in[4];
    const float* pv_b = (const float*)d_in[5];
    const float* n1w  = (const float*)d_in[6];
    const float* n1b  = (const float*)d_in[7];
    const float* n2w  = (const float*)d_in[8];
    const float* n2b  = (const float*)d_in[9];
    const float* n3w  = (const float*)d_in[10];
    const float* n3b  = (const float*)d_in[11];
    const float* n4w  = (const float*)d_in[12];
    const float* n4b  = (const float*)d_in[13];
    const float* qw   = (const float*)d_in[14];
    const float* kvw  = (const float*)d_in[15];
    const float* apw  = (const float*)d_in[16];
    const float* apb  = (const float*)d_in[17];
    const float* rpb  = (const float*)d_in[18];
    const float* f1w  = (const float*)d_in[19];
    const float* f1b  = (const float*)d_in[20];
    const float* f2w  = (const float*)d_in[21];
    const float* f2b  = (const float*)d_in[22];
    float* out = (float*)d_out;
    (void)in_sizes; (void)n_in; (void)out_size;

    float *xp,*vp,*xs,*vs,*q,*kv,*at,*pr,*l3,*h1,*m,*l4;
    cudaGetSymbolAddress((void**)&xp, g_xp);
    cudaGetSymbolAddress((void**)&vp, g_vp);
    cudaGetSymbolAddress((void**)&xs, g_xs);
    cudaGetSymbolAddress((void**)&vs, g_vs);
    cudaGetSymbolAddress((void**)&q , g_q );
    cudaGetSymbolAddress((void**)&kv, g_kv);
    cudaGetSymbolAddress((void**)&at, g_at);
    cudaGetSymbolAddress((void**)&pr, g_pr);
    cudaGetSymbolAddress((void**)&l3, g_l3);
    cudaGetSymbolAddress((void**)&h1, g_h1);
    cudaGetSymbolAddress((void**)&m , g_m );
    cudaGetSymbolAddress((void**)&l4, g_l4);

    const float SCALE = 0.20412414523193154f;  // 24^-0.5

    dim3 cgrid(4, 32, 12);
    conv3x3_kernel<<<cgrid,256>>>(x, pq_w, pq_b, xp);
    conv3x3_kernel<<<cgrid,256>>>(v, pv_w, pv_b, vp);

    ln_win_kernel<<<4096,256>>>(xp, n1w, n1b, xs);
    ln_win_kernel<<<4096,256>>>(vp, n2w, n2b, vs);

    sgemm_nt<false,false><<<dim3(3,2048),256>>>(xs, qw , nullptr, q , TT, CC,  CC, SCALE);
    sgemm_nt<false,false><<<dim3(6,2048),256>>>(vs, kvw, nullptr, kv, TT, 384, CC, 1.f);

    attn_kernel<<<2048,256>>>(q, kv, rpb, at);

    sgemm_nt<true ,false><<<dim3(3,2048),256>>>(at, apw, apb, pr, TT, CC, CC, 1.f);

    ln_rows_kernel<<<16384,256>>>(pr, n3w, n3b, l3);

    sgemm_nt<true ,true ><<<dim3(12,2048),256>>>(l3, f1w, f1b, h1, TT, FF, CC, 1.f);
    sgemm_nt<true ,false><<<dim3(3,2048),256>>>(h1, f2w, f2b, m , TT, CC, FF, 2.f);  // folds m=m+m

    ln_rows_kernel<<<16384,256>>>(m, n4w, n4b, l4);

    final_kernel<<<4096,256>>>(l4, xp, vp, out);
}

// round 2
// speedup vs baseline: 2.1603x; 2.1603x over previous
#include <cuda_runtime.h>
#include <math.h>
#include <stdint.h>

#define BB 8
#define CIN 96
#define CC 192
#define HH 128
#define WW 128
#define WS 8
#define HEADS 8
#define HD 24
#define TT 131072
#define FF 768
#define KCONV 864   // 9*96

// ---------------- scratch (device globals; no allocation allowed) ----------------
__device__ float g_nx[BB*CIN*HH*WW];       // x in NHWC
__device__ float g_nv[BB*CIN*HH*WW];       // v in NHWC
__device__ float g_xp[TT*CC];              // conv-q out, token layout
__device__ float g_vp[TT*CC];              // conv-v out, token layout
__device__ float g_xs[TT*CC];
__device__ float g_vs[TT*CC];
__device__ float g_q [TT*CC];
__device__ float g_kv[TT*2*CC];
__device__ float g_at[TT*CC];
__device__ float g_pr[TT*CC];
__device__ float g_l3[TT*CC];
__device__ float g_h1[(long)TT*FF];
__device__ float g_m [TT*CC];
__device__ float g_l4[TT*CC];
// transposed weights [K][N]
__device__ float g_qwT [CC*CC];
__device__ float g_kvwT[CC*2*CC];
__device__ float g_apwT[CC*CC];
__device__ float g_f1wT[CC*FF];
__device__ float g_f2wT[FF*CC];
__device__ float g_cqwT[KCONV*CC];
__device__ float g_cvwT[KCONV*CC];

// ---------------- helpers ----------------
__device__ __forceinline__ uint32_t f2tf(float x) {
    uint32_t r; asm("cvt.rna.tf32.f32 %0, %1;" : "=r"(r) : "f"(x)); return r;
}
__device__ __forceinline__ float tf2f(uint32_t x) { return __uint_as_float(x); }

__device__ __forceinline__ void mma_tf32(float* d, const uint32_t* a, const uint32_t* b, const float* c) {
    asm("mma.sync.aligned.m16n8k8.row.col.f32.tf32.tf32.f32 "
        "{%0,%1,%2,%3},{%4,%5,%6,%7},{%8,%9},{%10,%11,%12,%13};"
        : "=f"(d[0]), "=f"(d[1]), "=f"(d[2]), "=f"(d[3])
        : "r"(a[0]), "r"(a[1]), "r"(a[2]), "r"(a[3]),
          "r"(b[0]), "r"(b[1]),
          "f"(c[0]), "f"(c[1]), "f"(c[2]), "f"(c[3]));
}

// ---------------- weight prep ----------------
__global__ void transpose_w(const float* __restrict__ w, float* __restrict__ o, int N, int K) {
    int i = blockIdx.x * 256 + threadIdx.x;
    if (i < N * K) { int n = i / K, k = i % K; o[k * N + n] = w[i]; }
}
// (OC=192, C=96, 3, 3) -> [(ky*3+kx)*96 + c][oc]
__global__ void conv_wT(const float* __restrict__ w, float* __restrict__ o) {
    int i = blockIdx.x * 256 + threadIdx.x;
    if (i < CC * CIN * 9) {
        int oc = i / (CIN * 9), rem = i % (CIN * 9);
        int c = rem / 9, kk = rem % 9;
        o[(kk * CIN + c) * CC + oc] = w[i];
    }
}

// ---------------- NCHW -> NHWC ----------------
__global__ __launch_bounds__(256) void to_nhwc(const float* __restrict__ in, float* __restrict__ out) {
    __shared__ float tile[32][33];
    int by = blockIdx.z; int b = by >> 7, y = by & 127;
    int c0 = blockIdx.y * 32, x0 = blockIdx.x * 32;
    int tx = threadIdx.x, ty = threadIdx.y;  // 32 x 8
    #pragma unroll
    for (int i = ty; i < 32; i += 8)
        tile[i][tx] = in[((long)(b * CIN + c0 + i) * HH + y) * WW + x0 + tx];
    __syncthreads();
    #pragma unroll
    for (int i = ty; i < 32; i += 8)
        out[((long)(b * HH + y) * WW + x0 + i) * CIN + c0 + tx] = tile[tx][i];
}

// ---------------- tf32 MMA GEMM: C[M,N] = epi(A[M,K] @ BT[K,N]) ----------------
// block tile 128x64, 8 warps (4m x 2n), warp tile 32x32 (2x4 m16n8k8)
template<bool BIAS, bool GELU>
__global__ __launch_bounds__(256) void mm_tf32(
    const float* __restrict__ A, const float* __restrict__ BT,
    const float* __restrict__ bias, float* __restrict__ C,
    int M, int N, int K, float alpha)
{
    __shared__ float As[16][132];
    __shared__ float Bs[16][68];
    int tid = threadIdx.x;
    long bm = (long)blockIdx.y * 128;
    int bn = blockIdx.x * 64;
    int wid = tid >> 5, lane = tid & 31;
    int wm = wid >> 1, wn = wid & 1;
    int m0 = wm * 32, n0 = wn * 32;
    int g = lane >> 2, tg = lane & 3;

    float acc[2][4][4];
    #pragma unroll
    for (int i = 0; i < 2; i++)
        #pragma unroll
        for (int j = 0; j < 4; j++)
            #pragma unroll
            for (int r = 0; r < 4; r++) acc[i][j][r] = 0.f;

    int ar = tid >> 2, aseg = tid & 3;
    int bk = tid >> 4, bseg = tid & 15;

    for (int kt = 0; kt < K; kt += 16) {
        float4 va0 = *(const float4*)&A[(bm + ar) * K + kt + aseg * 4];
        float4 va1 = *(const float4*)&A[(bm + ar + 64) * K + kt + aseg * 4];
        float4 vb  = *(const float4*)&BT[(long)(kt + bk) * N + bn + bseg * 4];
        __syncthreads();
        As[aseg * 4 + 0][ar] = tf2f(f2tf(va0.x));
        As[aseg * 4 + 1][ar] = tf2f(f2tf(va0.y));
        As[aseg * 4 + 2][ar] = tf2f(f2tf(va0.z));
        As[aseg * 4 + 3][ar] = tf2f(f2tf(va0.w));
        As[aseg * 4 + 0][ar + 64] = tf2f(f2tf(va1.x));
        As[aseg * 4 + 1][ar + 64] = tf2f(f2tf(va1.y));
        As[aseg * 4 + 2][ar + 64] = tf2f(f2tf(va1.z));
        As[aseg * 4 + 3][ar + 64] = tf2f(f2tf(va1.w));
        float4 cb;
        cb.x = tf2f(f2tf(vb.x)); cb.y = tf2f(f2tf(vb.y));
        cb.z = tf2f(f2tf(vb.z)); cb.w = tf2f(f2tf(vb.w));
        *(float4*)&Bs[bk][bseg * 4] = cb;
        __syncthreads();
        #pragma unroll
        for (int kk = 0; kk < 16; kk += 8) {
            uint32_t af[2][4], bf[4][2];
            #pragma unroll
            for (int i = 0; i < 2; i++) {
                af[i][0] = __float_as_uint(As[kk + tg][m0 + i * 16 + g]);
                af[i][1] = __float_as_uint(As[kk + tg][m0 + i * 16 + g + 8]);
                af[i][2] = __float_as_uint(As[kk + tg + 4][m0 + i * 16 + g]);
                af[i][3] = __float_as_uint(As[kk + tg + 4][m0 + i * 16 + g + 8]);
            }
            #pragma unroll
            for (int j = 0; j < 4; j++) {
                bf[j][0] = __float_as_uint(Bs[kk + tg][n0 + j * 8 + g]);
                bf[j][1] = __float_as_uint(Bs[kk + tg + 4][n0 + j * 8 + g]);
            }
            #pragma unroll
            for (int i = 0; i < 2; i++)
                #pragma unroll
                for (int j = 0; j < 4; j++)
                    mma_tf32(acc[i][j], af[i], bf[j], acc[i][j]);
        }
    }
    #pragma unroll
    for (int i = 0; i < 2; i++) {
        long row0 = bm + m0 + i * 16 + g;
        #pragma unroll
        for (int j = 0; j < 4; j++) {
            int col = bn + n0 + j * 8 + 2 * tg;
            float b0 = 0.f, b1 = 0.f;
            if (BIAS) { b0 = bias[col]; b1 = bias[col + 1]; }
            #pragma unroll
            for (int half = 0; half < 2; half++) {
                long row = row0 + half * 8;
                float v0 = (acc[i][j][half * 2 + 0] + b0) * alpha;
                float v1 = (acc[i][j][half * 2 + 1] + b1) * alpha;
                if (GELU) {
                    v0 = 0.5f * v0 * (1.f + erff(v0 * 0.70710678118654752f));
                    v1 = 0.5f * v1 * (1.f + erff(v1 * 0.70710678118654752f));
                }
                float2 st = make_float2(v0, v1);
                *(float2*)&C[row * N + col] = st;
            }
        }
    }
}

// ---------------- conv3x3 as implicit GEMM (tf32 MMA), token-layout output ----------------
__global__ __launch_bounds__(256) void conv_tf32(
    const float* __restrict__ nhwc, const float* __restrict__ BT,
    const float* __restrict__ bias, float* __restrict__ C)
{
    __shared__ float As[16][132];
    __shared__ float Bs[16][68];
    const int N = CC;
    int tid = threadIdx.x;
    long bm = (long)blockIdx.y * 128;   // token base
    int bn = blockIdx.x * 64;
    int wid = tid >> 5, lane = tid & 31;
    int wm = wid >> 1, wn = wid & 1;
    int m0 = wm * 32, n0 = wn * 32;
    int g = lane >> 2, tg = lane & 3;

    float acc[2][4][4];
    #pragma unroll
    for (int i = 0; i < 2; i++)
        #pragma unroll
        for (int j = 0; j < 4; j++)
            #pragma unroll
            for (int r = 0; r < 4; r++) acc[i][j][r] = 0.f;

    int ar = tid >> 2, aseg = tid & 3;
    int bk = tid >> 4, bseg = tid & 15;

    // decode pixel coords for the two token rows this thread loads
    int xs_[2], ys_[2], bs_[2];
    #pragma unroll
    for (int h = 0; h < 2; h++) {
        long t = bm + ar + h * 64;
        int ix = t & 7, iy = (t >> 3) & 7, wx = (t >> 6) & 15, wy = (t >> 10) & 15;
        bs_[h] = (int)(t >> 14);
        xs_[h] = wx * 8 + ix;
        ys_[h] = wy * 8 + iy;
    }

    for (int kt = 0; kt < KCONV; kt += 16) {
        int ky = kt / 288, rem = kt % 288;
        int kx = rem / 96, c0 = rem % 96;
        float4 va[2];
        #pragma unroll
        for (int h = 0; h < 2; h++) {
            int sy = ys_[h] + ky - 1, sx = xs_[h] + kx - 1;
            if (sy >= 0 && sy < HH && sx >= 0 && sx < WW)
                va[h] = *(const float4*)&nhwc[((long)(bs_[h] * HH + sy) * WW + sx) * CIN + c0 + aseg * 4];
            else
                va[h] = make_float4(0.f, 0.f, 0.f, 0.f);
        }
        float4 vb = *(const float4*)&BT[(long)(kt + bk) * N + bn + bseg * 4];
        __syncthreads();
        #pragma unroll
        for (int h = 0; h < 2; h++) {
            As[aseg * 4 + 0][ar + h * 64] = tf2f(f2tf(va[h].x));
            As[aseg * 4 + 1][ar + h * 64] = tf2f(f2tf(va[h].y));
            As[aseg * 4 + 2][ar + h * 64] = tf2f(f2tf(va[h].z));
            As[aseg * 4 + 3][ar + h * 64] = tf2f(f2tf(va[h].w));
        }
        float4 cb;
        cb.x = tf2f(f2tf(vb.x)); cb.y = tf2f(f2tf(vb.y));
        cb.z = tf2f(f2tf(vb.z)); cb.w = tf2f(f2tf(vb.w));
        *(float4*)&Bs[bk][bseg * 4] = cb;
        __syncthreads();
        #pragma unroll
        for (int kk = 0; kk < 16; kk += 8) {
            uint32_t af[2][4], bf[4][2];
            #pragma unroll
            for (int i = 0; i < 2; i++) {
                af[i][0] = __float_as_uint(As[kk + tg][m0 + i * 16 + g]);
                af[i][1] = __float_as_uint(As[kk + tg][m0 + i * 16 + g + 8]);
                af[i][2] = __float_as_uint(As[kk + tg + 4][m0 + i * 16 + g]);
                af[i][3] = __float_as_uint(As[kk + tg + 4][m0 + i * 16 + g + 8]);
            }
            #pragma unroll
            for (int j = 0; j < 4; j++) {
                bf[j][0] = __float_as_uint(Bs[kk + tg][n0 + j * 8 + g]);
                bf[j][1] = __float_as_uint(Bs[kk + tg + 4][n0 + j * 8 + g]);
            }
            #pragma unroll
            for (int i = 0; i < 2; i++)
                #pragma unroll
                for (int j = 0; j < 4; j++)
                    mma_tf32(acc[i][j], af[i], bf[j], acc[i][j]);
        }
    }
    #pragma unroll
    for (int i = 0; i < 2; i++) {
        long row0 = bm + m0 + i * 16 + g;
        #pragma unroll
        for (int j = 0; j < 4; j++) {
            int col = bn + n0 + j * 8 + 2 * tg;
            float b0 = bias[col], b1 = bias[col + 1];
            #pragma unroll
            for (int half = 0; half < 2; half++) {
                long row = row0 + half * 8;
                float2 st = make_float2(acc[i][j][half * 2 + 0] + b0,
                                        acc[i][j][half * 2 + 1] + b1);
                *(float2*)&C[row * N + col] = st;
            }
        }
    }
}

// ---------------- windowed attention ----------------
__global__ __launch_bounds__(256) void attn_kernel(
    const float* __restrict__ q, const float* __restrict__ kv,
    const float* __restrict__ rpb, float* __restrict__ out)
{
    __shared__ float qs[64][25], ks[64][25], vs[64][25];
    __shared__ float sc[64][65];
    int w = blockIdx.x;
    int tid = threadIdx.x;
    long tb = (long)w * 64;
    for (int h = 0; h < HEADS; h++) {
        for (int e = tid; e < 64 * 24; e += 256) {
            int p = e / 24, d = e % 24;
            qs[p][d] = q [(tb + p) * CC       + h * HD + d];
            ks[p][d] = kv[(tb + p) * 2 * CC   + h * HD + d];
            vs[p][d] = kv[(tb + p) * 2 * CC + CC + h * HD + d];
        }
        __syncthreads();
        {
            int i = tid >> 2, jg = tid & 3;
            #pragma unroll
            for (int jj = 0; jj < 16; jj++) {
                int j = jg * 16 + jj;
                float s = 0.f;
                #pragma unroll
                for (int d = 0; d < 24; d++) s += qs[i][d] * ks[j][d];
                int ry = (i >> 3) - (j >> 3) + 7;
                int rx = (i & 7)  - (j & 7)  + 7;
                s += rpb[(ry * 15 + rx) * HEADS + h];
                sc[i][j] = s;
            }
        }
        __syncthreads();
        if (tid < 64) {
            float mx = -1e30f;
            for (int j = 0; j < 64; j++) mx = fmaxf(mx, sc[tid][j]);
            float sum = 0.f;
            for (int j = 0; j < 64; j++) { float e_ = expf(sc[tid][j] - mx); sc[tid][j] = e_; sum += e_; }
            float inv = 1.f / sum;
            for (int j = 0; j < 64; j++) sc[tid][j] *= inv;
        }
        __syncthreads();
        for (int e = tid; e < 64 * 24; e += 256) {
            int p = e / 24, d = e % 24;
            float s = 0.f;
            #pragma unroll
            for (int j = 0; j < 64; j++) s += sc[p][j] * vs[j][d];
            out[(tb + p) * CC + h * HD + d] = s;
        }
        __syncthreads();
    }
}

// ---------------- row LN over 192 channels (token-contiguous) ----------------
__global__ __launch_bounds__(256) void ln_rows_kernel(
    const float* __restrict__ in, const float* __restrict__ gamma,
    const float* __restrict__ beta, float* __restrict__ out)
{
    int warp = threadIdx.x >> 5, lane = threadIdx.x & 31;
    long row = (long)blockIdx.x * 8 + warp;
    const float* p = in + row * CC;
    float v[6];
    float sum = 0.f, sq = 0.f;
    #pragma unroll
    for (int k = 0; k < 6; k++) { v[k] = p[lane + k * 32]; sum += v[k]; sq += v[k] * v[k]; }
    #pragma unroll
    for (int o = 16; o > 0; o >>= 1) { sum += __shfl_xor_sync(~0u, sum, o); sq += __shfl_xor_sync(~0u, sq, o); }
    float mean = sum * (1.f / CC), var = sq * (1.f / CC) - mean * mean;
    float rstd = rsqrtf(var + 1e-5f);
    float* qo = out + row * CC;
    #pragma unroll
    for (int k = 0; k < 6; k++) { int c = lane + k * 32; qo[c] = (v[k] - mean) * rstd * gamma[c] + beta[c]; }
}

// ---------------- token layout -> NCHW with residual ----------------
__global__ __launch_bounds__(256) void final_kernel(
    const float* __restrict__ mln, const float* __restrict__ xp,
    const float* __restrict__ vp, float* __restrict__ out)
{
    __shared__ float s[128][33];
    int bx = blockIdx.x;                 // 0..6143
    int cch = bx % 6;                    // 32-channel chunk
    int by = bx / 6;
    int b = by >> 7, y = by & 127;
    int c0 = cch * 32;
    int tid = threadIdx.x;
    int wy = y >> 3, iy = y & 7;
    #pragma unroll
    for (int it = 0; it < 16; it++) {
        int e = tid + it * 256;
        int x = e >> 5, cl = e & 31;
        long t = (long)b * 16384 + (wy * 16 + (x >> 3)) * 64 + iy * 8 + (x & 7);
        long a = t * CC + c0 + cl;
        s[x][cl] = mln[a] + xp[a] + vp[a];
    }
    __syncthreads();
    #pragma unroll
    for (int it = 0; it < 16; it++) {
        int e = tid + it * 256;
        int x = e & 127, c = e >> 7;
        out[((long)(b * CC + c0 + c) * HH + y) * WW + x] = s[x][c];
    }
}

extern "C" void kernel_launch(void* const* d_in, const int* in_sizes, int n_in,
                              void* d_out, int out_size)
{
    const float* x    = (const float*)d_in[0];
    const float* v    = (const float*)d_in[1];
    const float* pq_w = (const float*)d_in[2];
    const float* pq_b = (const float*)d_in[3];
    const float* pv_w = (const float*)d_in[4];
    const float* pv_b = (const float*)d_in[5];
    const float* n1w  = (const float*)d_in[6];
    const float* n1b  = (const float*)d_in[7];
    const float* n2w  = (const float*)d_in[8];
    const float* n2b  = (const float*)d_in[9];
    const float* n3w  = (const float*)d_in[10];
    const float* n3b  = (const float*)d_in[11];
    const float* n4w  = (const float*)d_in[12];
    const float* n4b  = (const float*)d_in[13];
    const float* qw   = (const float*)d_in[14];
    const float* kvw  = (const float*)d_in[15];
    const float* apw  = (const float*)d_in[16];
    const float* apb  = (const float*)d_in[17];
    const float* rpb  = (const float*)d_in[18];
    const float* f1w  = (const float*)d_in[19];
    const float* f1b  = (const float*)d_in[20];
    const float* f2w  = (const float*)d_in[21];
    const float* f2b  = (const float*)d_in[22];
    float* out = (float*)d_out;
    (void)in_sizes; (void)n_in; (void)out_size;

    float *nx,*nv,*xp,*vp,*xs,*vs,*q,*kv,*at,*pr,*l3,*h1,*m,*l4;
    float *qwT,*kvwT,*apwT,*f1wT,*f2wT,*cqwT,*cvwT;
    cudaGetSymbolAddress((void**)&nx, g_nx);
    cudaGetSymbolAddress((void**)&nv, g_nv);
    cudaGetSymbolAddress((void**)&xp, g_xp);
    cudaGetSymbolAddress((void**)&vp, g_vp);
    cudaGetSymbolAddress((void**)&xs, g_xs);
    cudaGetSymbolAddress((void**)&vs, g_vs);
    cudaGetSymbolAddress((void**)&q , g_q );
    cudaGetSymbolAddress((void**)&kv, g_kv);
    cudaGetSymbolAddress((void**)&at, g_at);
    cudaGetSymbolAddress((void**)&pr, g_pr);
    cudaGetSymbolAddress((void**)&l3, g_l3);
    cudaGetSymbolAddress((void**)&h1, g_h1);
    cudaGetSymbolAddress((void**)&m , g_m );
    cudaGetSymbolAddress((void**)&l4, g_l4);
    cudaGetSymbolAddress((void**)&qwT , g_qwT );
    cudaGetSymbolAddress((void**)&kvwT, g_kvwT);
    cudaGetSymbolAddress((void**)&apwT, g_apwT);
    cudaGetSymbolAddress((void**)&f1wT, g_f1wT);
    cudaGetSymbolAddress((void**)&f2wT, g_f2wT);
    cudaGetSymbolAddress((void**)&cqwT, g_cqwT);
    cudaGetSymbolAddress((void**)&cvwT, g_cvwT);

    const float SCALE = 0.20412414523193154f;  // 24^-0.5

    // weight prep
    transpose_w<<<(CC*CC+255)/256,256>>>(qw , qwT , CC, CC);
    transpose_w<<<(2*CC*CC+255)/256,256>>>(kvw, kvwT, 2*CC, CC);
    transpose_w<<<(CC*CC+255)/256,256>>>(apw, apwT, CC, CC);
    transpose_w<<<(FF*CC+255)/256,256>>>(f1w, f1wT, FF, CC);
    transpose_w<<<(CC*FF+255)/256,256>>>(f2w, f2wT, CC, FF);
    conv_wT<<<(CC*CIN*9+255)/256,256>>>(pq_w, cqwT);
    conv_wT<<<(CC*CIN*9+255)/256,256>>>(pv_w, cvwT);

    // NHWC copies
    to_nhwc<<<dim3(4,3,1024),dim3(32,8)>>>(x, nx);
    to_nhwc<<<dim3(4,3,1024),dim3(32,8)>>>(v, nv);

    // convs as implicit GEMM -> token layout
    conv_tf32<<<dim3(3,1024),256>>>(nx, cqwT, pq_b, xp);
    conv_tf32<<<dim3(3,1024),256>>>(nv, cvwT, pv_b, vp);

    // LN1 / LN2
    ln_rows_kernel<<<16384,256>>>(xp, n1w, n1b, xs);
    ln_rows_kernel<<<16384,256>>>(vp, n2w, n2b, vs);

    // q / kv projections
    mm_tf32<false,false><<<dim3(3,1024),256>>>(xs, qwT , nullptr, q , TT, CC,  CC, SCALE);
    mm_tf32<false,false><<<dim3(6,1024),256>>>(vs, kvwT, nullptr, kv, TT, 2*CC, CC, 1.f);

    attn_kernel<<<2048,256>>>(q, kv, rpb, at);

    mm_tf32<true ,false><<<dim3(3,1024),256>>>(at, apwT, apb, pr, TT, CC, CC, 1.f);

    ln_rows_kernel<<<16384,256>>>(pr, n3w, n3b, l3);

    mm_tf32<true ,true ><<<dim3(12,1024),256>>>(l3, f1wT, f1b, h1, TT, FF, CC, 1.f);
    mm_tf32<true ,false><<<dim3(3,1024),256>>>(h1, f2wT, f2b, m , TT, CC, FF, 2.f);  // folds m=m+m

    ln_rows_kernel<<<16384,256>>>(m, n4w, n4b, l4);

    final_kernel<<<6144,256>>>(l4, xp, vp, out);
}

// round 3
// speedup vs baseline: 2.7919x; 1.2924x over previous
#include <cuda_runtime.h>
#include <math.h>
#include <stdint.h>

#define BB 8
#define CIN 96
#define CC 192
#define HH 128
#define WW 128
#define WS 8
#define HEADS 8
#define HD 24
#define TT 131072
#define FF 768
#define KCONV 864   // 9*96

// ---------------- scratch ----------------
__device__ float g_nx[BB*CIN*HH*WW];
__device__ float g_nv[BB*CIN*HH*WW];
__device__ float g_xp[TT*CC];
__device__ float g_vp[TT*CC];
__device__ float g_xs[TT*CC];
__device__ float g_vs[TT*CC];
__device__ float g_q [TT*CC];
__device__ float g_kv[TT*2*CC];
__device__ float g_at[TT*CC];
__device__ float g_pr[TT*CC];
__device__ float g_l3[TT*CC];
__device__ float g_h1[(long)TT*FF];
__device__ float g_m [TT*CC];
__device__ float g_l4[TT*CC];
__device__ float g_qwT [CC*CC];
__device__ float g_kvwT[CC*2*CC];
__device__ float g_apwT[CC*CC];
__device__ float g_f1wT[CC*FF];
__device__ float g_f2wT[FF*CC];
__device__ float g_cqwT[KCONV*CC];
__device__ float g_cvwT[KCONV*CC];

// ---------------- helpers ----------------
__device__ __forceinline__ uint32_t f2tf(float x) {
    uint32_t r; asm("cvt.rna.tf32.f32 %0, %1;" : "=r"(r) : "f"(x)); return r;
}
__device__ __forceinline__ float rnd(float x) { return __uint_as_float(f2tf(x)); }

__device__ __forceinline__ void mma_tf32(float* d, const uint32_t* a, const uint32_t* b, const float* c) {
    asm("mma.sync.aligned.m16n8k8.row.col.f32.tf32.tf32.f32 "
        "{%0,%1,%2,%3},{%4,%5,%6,%7},{%8,%9},{%10,%11,%12,%13};"
        : "=f"(d[0]), "=f"(d[1]), "=f"(d[2]), "=f"(d[3])
        : "r"(a[0]), "r"(a[1]), "r"(a[2]), "r"(a[3]),
          "r"(b[0]), "r"(b[1]),
          "f"(c[0]), "f"(c[1]), "f"(c[2]), "f"(c[3]));
}
__device__ __forceinline__ void cp16(uint32_t d, const void* s) {
    asm volatile("cp.async.cg.shared.global [%0], [%1], 16;" :: "r"(d), "l"(s));
}
__device__ __forceinline__ void cp16p(uint32_t d, const void* s, int sz) {
    asm volatile("cp.async.cg.shared.global [%0], [%1], 16, %2;" :: "r"(d), "l"(s), "r"(sz));
}
#define CP_COMMIT() asm volatile("cp.async.commit_group;")
#define CP_WAIT1()  asm volatile("cp.async.wait_group 1;")

// ---------------- fused weight prep (round to tf32 in memory) ----------------
#define S1 (CC*CC)
#define S2 (2*CC*CC)
#define S4 (FF*CC)
#define S6 (KCONV*CC)
__global__ void prep_weights(
    const float* __restrict__ qw, const float* __restrict__ kvw, const float* __restrict__ apw,
    const float* __restrict__ f1w, const float* __restrict__ f2w,
    const float* __restrict__ cqw, const float* __restrict__ cvw,
    float* __restrict__ qwT, float* __restrict__ kvwT, float* __restrict__ apwT,
    float* __restrict__ f1wT, float* __restrict__ f2wT,
    float* __restrict__ cqwT, float* __restrict__ cvwT)
{
    long i = (long)blockIdx.x * 256 + threadIdx.x;
    long o = i;
    if (o < S1) { int n=o/CC, k=o%CC; qwT[k*CC+n] = rnd(qw[o]); return; }
    o -= S1;
    if (o < S2) { int n=o/CC, k=o%CC; kvwT[(long)k*2*CC+n] = rnd(kvw[o]); return; }
    o -= S2;
    if (o < S1) { int n=o/CC, k=o%CC; apwT[k*CC+n] = rnd(apw[o]); return; }
    o -= S1;
    if (o < S4) { int n=o/CC, k=o%CC; f1wT[(long)k*FF+n] = rnd(f1w[o]); return; }
    o -= S4;
    if (o < S4) { int n=o/FF, k=o%FF; f2wT[(long)k*CC+n] = rnd(f2w[o]); return; }
    o -= S4;
    if (o < S6) { int oc=o/(CIN*9), rem=o%(CIN*9); int c=rem/9, kk=rem%9;
                  cqwT[((long)kk*CIN+c)*CC+oc] = rnd(cqw[o]); return; }
    o -= S6;
    if (o < S6) { int oc=o/(CIN*9), rem=o%(CIN*9); int c=rem/9, kk=rem%9;
                  cvwT[((long)kk*CIN+c)*CC+oc] = rnd(cvw[o]); return; }
}

// ---------------- NCHW -> NHWC (rounded) ----------------
__global__ __launch_bounds__(256) void to_nhwc(const float* __restrict__ in, float* __restrict__ out) {
    __shared__ float tile[32][33];
    int by = blockIdx.z; int b = by >> 7, y = by & 127;
    int c0 = blockIdx.y * 32, x0 = blockIdx.x * 32;
    int tx = threadIdx.x, ty = threadIdx.y;
    #pragma unroll
    for (int i = ty; i < 32; i += 8)
        tile[i][tx] = in[((long)(b * CIN + c0 + i) * HH + y) * WW + x0 + tx];
    __syncthreads();
    #pragma unroll
    for (int i = ty; i < 32; i += 8)
        out[((long)(b * HH + y) * WW + x0 + i) * CIN + c0 + tx] = rnd(tile[tx][i]);
}

// ---------------- tf32 MMA GEMM with cp.async double buffer ----------------
// operands pre-rounded to tf32 in memory. block 128x64, 8 warps, warp 32x32.
#define SA 20
#define SB 72
template<bool BIAS, bool GELU, bool ROUND>
__global__ __launch_bounds__(256) void mm_tf32(
    const float* __restrict__ A, const float* __restrict__ BT,
    const float* __restrict__ bias, float* __restrict__ C,
    int M, int N, int K, float alpha)
{
    __shared__ float As[2][128*SA];
    __shared__ float Bs[2][16*SB];
    int tid = threadIdx.x;
    long bm = (long)blockIdx.y * 128;
    int bn = blockIdx.x * 64;
    int wid = tid >> 5, lane = tid & 31;
    int wm = wid >> 1, wn = wid & 1;
    int m0 = wm * 32, n0 = wn * 32;
    int g = lane >> 2, tg = lane & 3;

    int ar = tid >> 2, aseg = tid & 3;
    int bk = tid >> 4, bseg = tid & 15;

    uint32_t sAa = (uint32_t)__cvta_generic_to_shared(&As[0][0]);
    uint32_t sBa = (uint32_t)__cvta_generic_to_shared(&Bs[0][0]);
    uint32_t dA0 = sAa + (ar * SA + aseg * 4) * 4;
    uint32_t dA1 = sAa + ((ar + 64) * SA + aseg * 4) * 4;
    uint32_t dB  = sBa + (bk * SB + bseg * 4) * 4;
    const float* pA0 = A + (bm + ar) * K + aseg * 4;
    const float* pA1 = A + (bm + ar + 64) * K + aseg * 4;
    const float* pB  = BT + (long)bk * N + bn + bseg * 4;
    const uint32_t stA = 128 * SA * 4, stB = 16 * SB * 4;

    float acc[2][4][4];
    #pragma unroll
    for (int i = 0; i < 2; i++)
        #pragma unroll
        for (int j = 0; j < 4; j++)
            #pragma unroll
            for (int r = 0; r < 4; r++) acc[i][j][r] = 0.f;

    cp16(dA0, pA0); cp16(dA1, pA1); cp16(dB, pB);
    CP_COMMIT();
    int NT = K / 16;
    for (int t = 0; t < NT; t++) {
        int buf = t & 1;
        if (t + 1 < NT) {
            int kt = (t + 1) * 16;
            int nb = buf ^ 1;
            cp16(dA0 + nb * stA, pA0 + kt);
            cp16(dA1 + nb * stA, pA1 + kt);
            cp16(dB  + nb * stB, pB + (long)kt * N);
        }
        CP_COMMIT();
        CP_WAIT1();
        __syncthreads();
        const float* as = As[buf];
        const float* bs = Bs[buf];
        #pragma unroll
        for (int kk = 0; kk < 16; kk += 8) {
            uint32_t af[2][4], bf[4][2];
            #pragma unroll
            for (int i = 0; i < 2; i++) {
                af[i][0] = __float_as_uint(as[(m0 + i*16 + g)     * SA + kk + tg]);
                af[i][1] = __float_as_uint(as[(m0 + i*16 + g + 8) * SA + kk + tg]);
                af[i][2] = __float_as_uint(as[(m0 + i*16 + g)     * SA + kk + tg + 4]);
                af[i][3] = __float_as_uint(as[(m0 + i*16 + g + 8) * SA + kk + tg + 4]);
            }
            #pragma unroll
            for (int j = 0; j < 4; j++) {
                bf[j][0] = __float_as_uint(bs[(kk + tg)     * SB + n0 + j*8 + g]);
                bf[j][1] = __float_as_uint(bs[(kk + tg + 4) * SB + n0 + j*8 + g]);
            }
            #pragma unroll
            for (int i = 0; i < 2; i++)
                #pragma unroll
                for (int j = 0; j < 4; j++)
                    mma_tf32(acc[i][j], af[i], bf[j], acc[i][j]);
        }
        __syncthreads();
    }
    #pragma unroll
    for (int i = 0; i < 2; i++) {
        long row0 = bm + m0 + i * 16 + g;
        #pragma unroll
        for (int j = 0; j < 4; j++) {
            int col = bn + n0 + j * 8 + 2 * tg;
            float b0 = 0.f, b1 = 0.f;
            if (BIAS) { b0 = bias[col]; b1 = bias[col + 1]; }
            #pragma unroll
            for (int half = 0; half < 2; half++) {
                long row = row0 + half * 8;
                float v0 = (acc[i][j][half * 2 + 0] + b0) * alpha;
                float v1 = (acc[i][j][half * 2 + 1] + b1) * alpha;
                if (GELU) {
                    v0 = 0.5f * v0 * (1.f + erff(v0 * 0.70710678118654752f));
                    v1 = 0.5f * v1 * (1.f + erff(v1 * 0.70710678118654752f));
                }
                if (ROUND) { v0 = rnd(v0); v1 = rnd(v1); }
                *(float2*)&C[row * N + col] = make_float2(v0, v1);
            }
        }
    }
}

// ---------------- conv3x3 implicit GEMM, cp.async double buffer ----------------
__global__ __launch_bounds__(256) void conv_tf32(
    const float* __restrict__ nhwc, const float* __restrict__ BT,
    const float* __restrict__ bias, float* __restrict__ C)
{
    __shared__ float As[2][128*SA];
    __shared__ float Bs[2][16*SB];
    const int N = CC;
    int tid = threadIdx.x;
    long bm = (long)blockIdx.y * 128;
    int bn = blockIdx.x * 64;
    int wid = tid >> 5, lane = tid & 31;
    int wm = wid >> 1, wn = wid & 1;
    int m0 = wm * 32, n0 = wn * 32;
    int g = lane >> 2, tg = lane & 3;

    int ar = tid >> 2, aseg = tid & 3;
    int bk = tid >> 4, bseg = tid & 15;

    uint32_t sAa = (uint32_t)__cvta_generic_to_shared(&As[0][0]);
    uint32_t sBa = (uint32_t)__cvta_generic_to_shared(&Bs[0][0]);
    uint32_t dA0 = sAa + (ar * SA + aseg * 4) * 4;
    uint32_t dA1 = sAa + ((ar + 64) * SA + aseg * 4) * 4;
    uint32_t dB  = sBa + (bk * SB + bseg * 4) * 4;
    const float* pB = BT + (long)bk * N + bn + bseg * 4;
    const uint32_t stA = 128 * SA * 4, stB = 16 * SB * 4;

    int xs_[2], ys_[2], bs_[2];
    #pragma unroll
    for (int h = 0; h < 2; h++) {
        long t = bm + ar + h * 64;
        int ix = t & 7, iy = (t >> 3) & 7, wx = (t >> 6) & 15, wy = (t >> 10) & 15;
        bs_[h] = (int)(t >> 14);
        xs_[h] = wx * 8 + ix;
        ys_[h] = wy * 8 + iy;
    }

    float acc[2][4][4];
    #pragma unroll
    for (int i = 0; i < 2; i++)
        #pragma unroll
        for (int j = 0; j < 4; j++)
            #pragma unroll
            for (int r = 0; r < 4; r++) acc[i][j][r] = 0.f;

    // prologue: tile 0 (kt=0 -> ky=0,kx=0)
    {
        #pragma unroll
        for (int h = 0; h < 2; h++) {
            int sy = ys_[h] - 1, sx = xs_[h] - 1;
            bool ok = (sy >= 0) && (sx >= 0);
            const float* src = ok ? &nhwc[((long)(bs_[h] * HH + sy) * WW + sx) * CIN + aseg * 4] : nhwc;
            cp16p((h ? dA1 : dA0), src, ok ? 16 : 0);
        }
        cp16(dB, pB);
        CP_COMMIT();
    }
    const int NT = KCONV / 16;
    for (int t = 0; t < NT; t++) {
        int buf = t & 1;
        if (t + 1 < NT) {
            int kt = (t + 1) * 16;
            int ky = kt / 288, rem = kt % 288;
            int kx = rem / 96, c0 = rem % 96;
            int nb = buf ^ 1;
            #pragma unroll
            for (int h = 0; h < 2; h++) {
                int sy = ys_[h] + ky - 1, sx = xs_[h] + kx - 1;
                bool ok = (sy >= 0) && (sy < HH) && (sx >= 0) && (sx < WW);
                const float* src = ok ? &nhwc[((long)(bs_[h] * HH + sy) * WW + sx) * CIN + c0 + aseg * 4] : nhwc;
                cp16p((h ? dA1 : dA0) + nb * stA, src, ok ? 16 : 0);
            }
            cp16(dB + nb * stB, pB + (long)kt * N);
        }
        CP_COMMIT();
        CP_WAIT1();
        __syncthreads();
        const float* as = As[buf];
        const float* bs = Bs[buf];
        #pragma unroll
        for (int kk = 0; kk < 16; kk += 8) {
            uint32_t af[2][4], bf[4][2];
            #pragma unroll
            for (int i = 0; i < 2; i++) {
                af[i][0] = __float_as_uint(as[(m0 + i*16 + g)     * SA + kk + tg]);
                af[i][1] = __float_as_uint(as[(m0 + i*16 + g + 8) * SA + kk + tg]);
                af[i][2] = __float_as_uint(as[(m0 + i*16 + g)     * SA + kk + tg + 4]);
                af[i][3] = __float_as_uint(as[(m0 + i*16 + g + 8) * SA + kk + tg + 4]);
            }
            #pragma unroll
            for (int j = 0; j < 4; j++) {
                bf[j][0] = __float_as_uint(bs[(kk + tg)     * SB + n0 + j*8 + g]);
                bf[j][1] = __float_as_uint(bs[(kk + tg + 4) * SB + n0 + j*8 + g]);
            }
            #pragma unroll
            for (int i = 0; i < 2; i++)
                #pragma unroll
                for (int j = 0; j < 4; j++)
                    mma_tf32(acc[i][j], af[i], bf[j], acc[i][j]);
        }
        __syncthreads();
    }
    #pragma unroll
    for (int i = 0; i < 2; i++) {
        long row0 = bm + m0 + i * 16 + g;
        #pragma unroll
        for (int j = 0; j < 4; j++) {
            int col = bn + n0 + j * 8 + 2 * tg;
            float b0 = bias[col], b1 = bias[col + 1];
            #pragma unroll
            for (int half = 0; half < 2; half++) {
                long row = row0 + half * 8;
                *(float2*)&C[row * N + col] =
                    make_float2(acc[i][j][half*2+0] + b0, acc[i][j][half*2+1] + b1);
            }
        }
    }
}

// ---------------- windowed attention ----------------
__global__ __launch_bounds__(256) void attn_kernel(
    const float* __restrict__ q, const float* __restrict__ kv,
    const float* __restrict__ rpb, float* __restrict__ out)
{
    __shared__ float qs[64][25], ks[64][25], vs[64][25];
    __shared__ float sc[64][65];
    __shared__ float s_rpb[225][8];
    int w = blockIdx.x;
    int tid = threadIdx.x;
    long tb = (long)w * 64;
    for (int e = tid; e < 225 * 8; e += 256) s_rpb[e >> 3][e & 7] = rpb[e];
    for (int h = 0; h < HEADS; h++) {
        for (int e = tid; e < 64 * 24; e += 256) {
            int p = e / 24, d = e % 24;
            qs[p][d] = q [(tb + p) * CC          + h * HD + d];
            ks[p][d] = kv[(tb + p) * 2 * CC      + h * HD + d];
            vs[p][d] = kv[(tb + p) * 2 * CC + CC + h * HD + d];
        }
        __syncthreads();
        {
            int i = tid >> 2, l = tid & 3;
            #pragma unroll
            for (int jj = 0; jj < 16; jj++) {
                int j = l * 16 + jj;
                float s = 0.f;
                #pragma unroll
                for (int d = 0; d < 24; d++) s += qs[i][d] * ks[j][d];
                int ry = (i >> 3) - (j >> 3) + 7;
                int rx = (i & 7)  - (j & 7)  + 7;
                s += s_rpb[ry * 15 + rx][h];
                sc[i][j] = s;
            }
            // softmax: 4 lanes per row (same quad), no block sync needed
            float mx = -1e30f;
            #pragma unroll
            for (int jj = 0; jj < 16; jj++) mx = fmaxf(mx, sc[i][l * 16 + jj]);
            mx = fmaxf(mx, __shfl_xor_sync(~0u, mx, 1));
            mx = fmaxf(mx, __shfl_xor_sync(~0u, mx, 2));
            float sum = 0.f;
            #pragma unroll
            for (int jj = 0; jj < 16; jj++) {
                float e_ = __expf(sc[i][l * 16 + jj] - mx);
                sc[i][l * 16 + jj] = e_; sum += e_;
            }
            sum += __shfl_xor_sync(~0u, sum, 1);
            sum += __shfl_xor_sync(~0u, sum, 2);
            float inv = 1.f / sum;
            #pragma unroll
            for (int jj = 0; jj < 16; jj++) sc[i][l * 16 + jj] *= inv;
        }
        __syncthreads();
        for (int e = tid; e < 64 * 24; e += 256) {
            int p = e / 24, d = e % 24;
            float s = 0.f;
            #pragma unroll
            for (int j = 0; j < 64; j++) s += sc[p][j] * vs[j][d];
            out[(tb + p) * CC + h * HD + d] = rnd(s);
        }
        __syncthreads();
    }
}

// ---------------- row LN ----------------
template<bool ROUND>
__global__ __launch_bounds__(256) void ln_rows_kernel(
    const float* __restrict__ in, const float* __restrict__ gamma,
    const float* __restrict__ beta, float* __restrict__ out)
{
    int warp = threadIdx.x >> 5, lane = threadIdx.x & 31;
    long row = (long)blockIdx.x * 8 + warp;
    const float* p = in + row * CC;
    float v[6];
    float sum = 0.f, sq = 0.f;
    #pragma unroll
    for (int k = 0; k < 6; k++) { v[k] = p[lane + k * 32]; sum += v[k]; sq += v[k] * v[k]; }
    #pragma unroll
    for (int o = 16; o > 0; o >>= 1) { sum += __shfl_xor_sync(~0u, sum, o); sq += __shfl_xor_sync(~0u, sq, o); }
    float mean = sum * (1.f / CC), var = sq * (1.f / CC) - mean * mean;
    float rstd = rsqrtf(var + 1e-5f);
    float* qo = out + row * CC;
    #pragma unroll
    for (int k = 0; k < 6; k++) {
        int c = lane + k * 32;
        float r = (v[k] - mean) * rstd * gamma[c] + beta[c];
        qo[c] = ROUND ? rnd(r) : r;
    }
}

// ---------------- token layout -> NCHW with residual ----------------
__global__ __launch_bounds__(256) void final_kernel(
    const float* __restrict__ mln, const float* __restrict__ xp,
    const float* __restrict__ vp, float* __restrict__ out)
{
    __shared__ float s[128][33];
    int bx = blockIdx.x;
    int cch = bx % 6;
    int by = bx / 6;
    int b = by >> 7, y = by & 127;
    int c0 = cch * 32;
    int tid = threadIdx.x;
    int wy = y >> 3, iy = y & 7;
    #pragma unroll
    for (int it = 0; it < 16; it++) {
        int e = tid + it * 256;
        int x = e >> 5, cl = e & 31;
        long t = (long)b * 16384 + (wy * 16 + (x >> 3)) * 64 + iy * 8 + (x & 7);
        long a = t * CC + c0 + cl;
        s[x][cl] = mln[a] + xp[a] + vp[a];
    }
    __syncthreads();
    #pragma unroll
    for (int it = 0; it < 16; it++) {
        int e = tid + it * 256;
        int x = e & 127, c = e >> 7;
        out[((long)(b * CC + c0 + c) * HH + y) * WW + x] = s[x][c];
    }
}

extern "C" void kernel_launch(void* const* d_in, const int* in_sizes, int n_in,
                              void* d_out, int out_size)
{
    const float* x    = (const float*)d_in[0];
    const float* v    = (const float*)d_in[1];
    const float* pq_w = (const float*)d_in[2];
    const float* pq_b = (const float*)d_in[3];
    const float* pv_w = (const float*)d_in[4];
    const float* pv_b = (const float*)d_in[5];
    const float* n1w  = (const float*)d_in[6];
    const float* n1b  = (const float*)d_in[7];
    const float* n2w  = (const float*)d_in[8];
    const float* n2b  = (const float*)d_in[9];
    const float* n3w  = (const float*)d_in[10];
    const float* n3b  = (const float*)d_in[11];
    const float* n4w  = (const float*)d_in[12];
    const float* n4b  = (const float*)d_in[13];
    const float* qw   = (const float*)d_in[14];
    const float* kvw  = (const float*)d_in[15];
    const float* apw  = (const float*)d_in[16];
    const float* apb  = (const float*)d_in[17];
    const float* rpb  = (const float*)d_in[18];
    const float* f1w  = (const float*)d_in[19];
    const float* f1b  = (const float*)d_in[20];
    const float* f2w  = (const float*)d_in[21];
    const float* f2b  = (const float*)d_in[22];
    float* out = (float*)d_out;
    (void)in_sizes; (void)n_in; (void)out_size;

    float *nx,*nv,*xp,*vp,*xs,*vs,*q,*kv,*at,*pr,*l3,*h1,*m,*l4;
    float *qwT,*kvwT,*apwT,*f1wT,*f2wT,*cqwT,*cvwT;
    cudaGetSymbolAddress((void**)&nx, g_nx);
    cudaGetSymbolAddress((void**)&nv, g_nv);
    cudaGetSymbolAddress((void**)&xp, g_xp);
    cudaGetSymbolAddress((void**)&vp, g_vp);
    cudaGetSymbolAddress((void**)&xs, g_xs);
    cudaGetSymbolAddress((void**)&vs, g_vs);
    cudaGetSymbolAddress((void**)&q , g_q );
    cudaGetSymbolAddress((void**)&kv, g_kv);
    cudaGetSymbolAddress((void**)&at, g_at);
    cudaGetSymbolAddress((void**)&pr, g_pr);
    cudaGetSymbolAddress((void**)&l3, g_l3);
    cudaGetSymbolAddress((void**)&h1, g_h1);
    cudaGetSymbolAddress((void**)&m , g_m );
    cudaGetSymbolAddress((void**)&l4, g_l4);
    cudaGetSymbolAddress((void**)&qwT , g_qwT );
    cudaGetSymbolAddress((void**)&kvwT, g_kvwT);
    cudaGetSymbolAddress((void**)&apwT, g_apwT);
    cudaGetSymbolAddress((void**)&f1wT, g_f1wT);
    cudaGetSymbolAddress((void**)&f2wT, g_f2wT);
    cudaGetSymbolAddress((void**)&cqwT, g_cqwT);
    cudaGetSymbolAddress((void**)&cvwT, g_cvwT);

    const float SCALE = 0.20412414523193154f;  // 24^-0.5

    long totalW = (long)S1 + S2 + S1 + S4 + S4 + S6 + S6;
    prep_weights<<<(int)((totalW + 255) / 256), 256>>>(
        qw, kvw, apw, f1w, f2w, pq_w, pv_w,
        qwT, kvwT, apwT, f1wT, f2wT, cqwT, cvwT);

    to_nhwc<<<dim3(4,3,1024),dim3(32,8)>>>(x, nx);
    to_nhwc<<<dim3(4,3,1024),dim3(32,8)>>>(v, nv);

    conv_tf32<<<dim3(3,1024),256>>>(nx, cqwT, pq_b, xp);
    conv_tf32<<<dim3(3,1024),256>>>(nv, cvwT, pv_b, vp);

    ln_rows_kernel<true><<<16384,256>>>(xp, n1w, n1b, xs);
    ln_rows_kernel<true><<<16384,256>>>(vp, n2w, n2b, vs);

    mm_tf32<false,false,false><<<dim3(3,1024),256>>>(xs, qwT , nullptr, q , TT, CC,   CC, SCALE);
    mm_tf32<false,false,false><<<dim3(6,1024),256>>>(vs, kvwT, nullptr, kv, TT, 2*CC, CC, 1.f);

    attn_kernel<<<2048,256>>>(q, kv, rpb, at);

    mm_tf32<true,false,false><<<dim3(3,1024),256>>>(at, apwT, apb, pr, TT, CC, CC, 1.f);

    ln_rows_kernel<true><<<16384,256>>>(pr, n3w, n3b, l3);

    mm_tf32<true,true ,true ><<<dim3(12,1024),256>>>(l3, f1wT, f1b, h1, TT, FF, CC, 1.f);
    mm_tf32<true,false,false><<<dim3(3,1024),256>>>(h1, f2wT, f2b, m , TT, CC, FF, 2.f);

    ln_rows_kernel<false><<<16384,256>>>(m, n4w, n4b, l4);

    final_kernel<<<6144,256>>>(l4, xp, vp, out);
}